// round 1
// baseline (speedup 1.0000x reference)
#include <cuda_runtime.h>
#include <math.h>

// ---------------------------------------------------------------------------
// Problem constants
// ---------------------------------------------------------------------------
#define BB 32
#define SS 256
#define MM (BB*SS)        // 8192 rows
#define DD 768
#define HH 12
#define DHD 64
#define FFD 3072
#define LL 12
#define NSENSE 64
#define NATT 64

// ---------------------------------------------------------------------------
// Scratch (static __device__ arrays; no runtime allocation allowed)
// ---------------------------------------------------------------------------
__device__ float g_x  [(size_t)MM*DD];
__device__ float g_q  [(size_t)MM*DD];
__device__ float g_k  [(size_t)MM*DD];
__device__ float g_v  [(size_t)MM*DD];
__device__ float g_att[(size_t)MM*DD];
__device__ float g_tmp[(size_t)MM*DD];
__device__ float g_ffn[(size_t)MM*FFD];
__device__ float g_sk [NSENSE*NATT];

// ---------------------------------------------------------------------------
// Embedding + LayerNorm:  x = LN(word[id] + pos[s] + type[tt]) * g + b
// one block per row (8192 blocks, 256 threads)
// ---------------------------------------------------------------------------
__global__ __launch_bounds__(256)
void embed_ln_kernel(const int* __restrict__ ids, const int* __restrict__ tt,
                     const float* __restrict__ we, const float* __restrict__ pe,
                     const float* __restrict__ te, const float* __restrict__ lg,
                     const float* __restrict__ lb, float* __restrict__ x)
{
    int row = blockIdx.x;
    int s   = row % SS;
    int id  = ids[row];
    int t   = tt[row];
    int tid = threadIdx.x;

    const float* wr = we + (size_t)id * DD;
    const float* pr = pe + (size_t)s  * DD;
    const float* tr = te + (size_t)t  * DD;

    float v[3];
    float sum = 0.f, sq = 0.f;
#pragma unroll
    for (int i = 0; i < 3; i++) {
        int d = tid + i * 256;
        float y = wr[d] + pr[d] + tr[d];
        v[i] = y; sum += y; sq += y * y;
    }
    __shared__ float sh1[256], sh2[256];
    sh1[tid] = sum; sh2[tid] = sq;
    __syncthreads();
    for (int st = 128; st > 0; st >>= 1) {
        if (tid < st) { sh1[tid] += sh1[tid+st]; sh2[tid] += sh2[tid+st]; }
        __syncthreads();
    }
    float mu  = sh1[0] * (1.f/768.f);
    float var = fmaxf(sh2[0] * (1.f/768.f) - mu*mu, 0.f);
    float inv = rsqrtf(var + 1e-12f);
#pragma unroll
    for (int i = 0; i < 3; i++) {
        int d = tid + i * 256;
        x[(size_t)row*DD + d] = (v[i]-mu)*inv*lg[d] + lb[d];
    }
}

// ---------------------------------------------------------------------------
// Residual + bias + LayerNorm (in-place on x):
//   x = LN(x + val + bias) * g + b
// ---------------------------------------------------------------------------
__global__ __launch_bounds__(256)
void ln_res_kernel(float* __restrict__ x, const float* __restrict__ val,
                   const float* __restrict__ bias, const float* __restrict__ lg,
                   const float* __restrict__ lb)
{
    int row = blockIdx.x;
    int tid = threadIdx.x;
    float v[3];
    float sum = 0.f, sq = 0.f;
#pragma unroll
    for (int i = 0; i < 3; i++) {
        int d = tid + i * 256;
        float y = x[(size_t)row*DD + d] + val[(size_t)row*DD + d] + bias[d];
        v[i] = y; sum += y; sq += y * y;
    }
    __shared__ float sh1[256], sh2[256];
    sh1[tid] = sum; sh2[tid] = sq;
    __syncthreads();
    for (int st = 128; st > 0; st >>= 1) {
        if (tid < st) { sh1[tid] += sh1[tid+st]; sh2[tid] += sh2[tid+st]; }
        __syncthreads();
    }
    float mu  = sh1[0] * (1.f/768.f);
    float var = fmaxf(sh2[0] * (1.f/768.f) - mu*mu, 0.f);
    float inv = rsqrtf(var + 1e-12f);
#pragma unroll
    for (int i = 0; i < 3; i++) {
        int d = tid + i * 256;
        x[(size_t)row*DD + d] = (v[i]-mu)*inv*lg[d] + lb[d];
    }
}

// ---------------------------------------------------------------------------
// GEMM: C[M,N] = A[M,K] @ W[K,N]  (+bias) (+gelu)
// 128x128x16 tiles, 256 threads, 8x8 micro-tile.
// MODE 0: plain   MODE 1: +bias   MODE 2: +bias then exact gelu
// M is fixed at 8192 via gridDim.y*128; M,N,K all divisible by tile dims.
// ---------------------------------------------------------------------------
__device__ __forceinline__ float gelu_exact(float x) {
    return 0.5f * x * (1.0f + erff(x * 0.70710678118654752f));
}

template<int MODE>
__global__ __launch_bounds__(256)
void gemm_kernel(const float* __restrict__ A, const float* __restrict__ W,
                 const float* __restrict__ bias, float* __restrict__ C,
                 int N, int K)
{
    __shared__ float As[16][128];
    __shared__ float Ws[16][128];

    int tid = threadIdx.x;
    int bm = blockIdx.y * 128;
    int bn = blockIdx.x * 128;
    int tx = tid & 15;     // 0..15 (col group)
    int ty = tid >> 4;     // 0..15 (row group)

    float acc[8][8];
#pragma unroll
    for (int i = 0; i < 8; i++)
#pragma unroll
        for (int j = 0; j < 8; j++) acc[i][j] = 0.f;

    const float* Ablk = A + (size_t)bm * K;
    const float* Wblk = W + bn;

    for (int k0 = 0; k0 < K; k0 += 16) {
#pragma unroll
        for (int c = 0; c < 2; c++) {
            int f = tid + c * 256;            // 0..511  (float4 index)
            // A tile: 128 rows x 16 k  -> transposed into As[k][m]
            int m  = f >> 2;                  // 0..127
            int kc = (f & 3) << 2;            // 0,4,8,12
            float4 a4 = *(const float4*)(Ablk + (size_t)m * K + k0 + kc);
            As[kc+0][m] = a4.x; As[kc+1][m] = a4.y;
            As[kc+2][m] = a4.z; As[kc+3][m] = a4.w;
            // W tile: 16 k x 128 n
            int kr = f >> 5;                  // 0..15
            int nc = (f & 31) << 2;           // 0..124
            *(float4*)&Ws[kr][nc] = *(const float4*)(Wblk + (size_t)(k0+kr) * N + nc);
        }
        __syncthreads();

#pragma unroll
        for (int kk = 0; kk < 16; kk++) {
            float a[8], b[8];
            *(float4*)(a)   = *(const float4*)&As[kk][ty*8];
            *(float4*)(a+4) = *(const float4*)&As[kk][ty*8+4];
            *(float4*)(b)   = *(const float4*)&Ws[kk][tx*8];
            *(float4*)(b+4) = *(const float4*)&Ws[kk][tx*8+4];
#pragma unroll
            for (int i = 0; i < 8; i++)
#pragma unroll
                for (int j = 0; j < 8; j++)
                    acc[i][j] += a[i] * b[j];
        }
        __syncthreads();
    }

    // epilogue
#pragma unroll
    for (int i = 0; i < 8; i++) {
        int row = bm + ty*8 + i;
        float* crow = C + (size_t)row * N + bn + tx*8;
        float out[8];
#pragma unroll
        for (int j = 0; j < 8; j++) {
            float vv = acc[i][j];
            if (MODE >= 1) vv += bias[bn + tx*8 + j];
            if (MODE == 2) vv = gelu_exact(vv);
            out[j] = vv;
        }
        *(float4*)(crow)   = *(float4*)(out);
        *(float4*)(crow+4) = *(float4*)(out+4);
    }
}

// ---------------------------------------------------------------------------
// Attention: one block per (q, h, b). 256 threads.
//   scores_j = (q . k_j)/8 + maskbias_j ; softmax ; o = attn @ V
// ---------------------------------------------------------------------------
__global__ __launch_bounds__(256)
void attn_kernel(const float* __restrict__ q, const float* __restrict__ k,
                 const float* __restrict__ v, const int* __restrict__ mask,
                 float* __restrict__ o)
{
    int qi = blockIdx.x, h = blockIdx.y, b = blockIdx.z;
    int tid = threadIdx.x;

    __shared__ float qs[DHD];
    __shared__ float att[SS];
    __shared__ float red[256];
    __shared__ float osum[4][DHD];

    if (tid < DHD)
        qs[tid] = q[((size_t)(b*SS + qi))*DD + h*DHD + tid];
    __syncthreads();

    // scores: thread tid handles key tid
    const float* kp = k + ((size_t)(b*SS + tid))*DD + h*DHD;
    float s = 0.f;
#pragma unroll
    for (int d = 0; d < DHD; d++) s += qs[d] * kp[d];
    s *= 0.125f;
    s += (1.0f - (float)mask[b*SS + tid]) * -10000.0f;

    // softmax (max)
    red[tid] = s; __syncthreads();
    for (int st = 128; st > 0; st >>= 1) {
        if (tid < st) red[tid] = fmaxf(red[tid], red[tid+st]);
        __syncthreads();
    }
    float mx = red[0];
    __syncthreads();
    float e = expf(s - mx);
    att[tid] = e;
    red[tid] = e; __syncthreads();
    for (int st = 128; st > 0; st >>= 1) {
        if (tid < st) red[tid] += red[tid+st];
        __syncthreads();
    }
    float inv = 1.0f / red[0];

    // o accumulation: 4 key-groups x 64 dims
    int gr = tid >> 6, d = tid & 63;
    const float* vp = v + ((size_t)(b*SS + gr*64))*DD + h*DHD + d;
    float acc = 0.f;
#pragma unroll 8
    for (int j = 0; j < 64; j++)
        acc += att[gr*64 + j] * vp[(size_t)j * DD];
    osum[gr][d] = acc;
    __syncthreads();
    if (tid < DHD) {
        float r = (osum[0][tid]+osum[1][tid]+osum[2][tid]+osum[3][tid]) * inv;
        o[((size_t)(b*SS + qi))*DD + h*DHD + tid] = r;
    }
}

// ---------------------------------------------------------------------------
// sense key projection: sk[j,t] = sum_d sense[j,d] * att_Wk[d,t]
// ---------------------------------------------------------------------------
__global__ __launch_bounds__(64)
void sense_k_kernel(const float* __restrict__ sense, const float* __restrict__ Wk,
                    float* __restrict__ sk)
{
    int j = blockIdx.x, t = threadIdx.x;
    float s = 0.f;
    for (int d = 0; d < DD; d++)
        s += sense[(size_t)j*DD + d] * Wk[(size_t)d*NATT + t];
    sk[j*NATT + t] = s;
}

// ---------------------------------------------------------------------------
// final: gather pun row, project by att_Wq, score vs sk, top-2 indices
// ---------------------------------------------------------------------------
__global__ __launch_bounds__(64)
void final_kernel(const float* __restrict__ x, const int* __restrict__ loc,
                  const float* __restrict__ Wq, const float* __restrict__ sk,
                  float* __restrict__ out)
{
    int b = blockIdx.x, t = threadIdx.x;
    __shared__ float pun[DD];
    __shared__ float pq[NATT];
    __shared__ float sc[NSENSE];

    int r = b*SS + loc[b];
    for (int d = t; d < DD; d += 64) pun[d] = x[(size_t)r*DD + d];
    __syncthreads();

    float s = 0.f;
    for (int d = 0; d < DD; d++) s += pun[d] * Wq[(size_t)d*NATT + t];
    pq[t] = s;
    __syncthreads();

    float sv = 0.f;
#pragma unroll
    for (int u = 0; u < NATT; u++) sv += pq[u] * sk[t*NATT + u];
    sc[t] = sv * 0.125f;   // /sqrt(64); monotone for top-k anyway
    __syncthreads();

    if (t == 0) {
        int i1 = 0; float b1v = sc[0];
        for (int i = 1; i < NSENSE; i++) if (sc[i] > b1v) { b1v = sc[i]; i1 = i; }
        int i2 = -1; float b2v = -3.4e38f;
        for (int i = 0; i < NSENSE; i++) if (i != i1 && sc[i] > b2v) { b2v = sc[i]; i2 = i; }
        out[b*2+0] = (float)i1;
        out[b*2+1] = (float)i2;
    }
}

// ---------------------------------------------------------------------------
// launch
// ---------------------------------------------------------------------------
extern "C" void kernel_launch(void* const* d_in, const int* in_sizes, int n_in,
                              void* d_out, int out_size)
{
    const int*   input_ids = (const int*)  d_in[0];
    const int*   type_ids  = (const int*)  d_in[1];
    const int*   attn_mask = (const int*)  d_in[2];
    const int*   location  = (const int*)  d_in[3];
    const float* sense_emb = (const float*)d_in[4];
    const float* word_emb  = (const float*)d_in[5];
    const float* pos_emb   = (const float*)d_in[6];
    const float* type_emb  = (const float*)d_in[7];
    const float* emb_ln_g  = (const float*)d_in[8];
    const float* emb_ln_b  = (const float*)d_in[9];
    const float* Wq = (const float*)d_in[10];
    const float* bq = (const float*)d_in[11];
    const float* Wk = (const float*)d_in[12];
    const float* bk = (const float*)d_in[13];
    const float* Wv = (const float*)d_in[14];
    const float* bv = (const float*)d_in[15];
    const float* Wo = (const float*)d_in[16];
    const float* bo = (const float*)d_in[17];
    const float* ln1_g = (const float*)d_in[18];
    const float* ln1_b = (const float*)d_in[19];
    const float* W1 = (const float*)d_in[20];
    const float* b1 = (const float*)d_in[21];
    const float* W2 = (const float*)d_in[22];
    const float* b2 = (const float*)d_in[23];
    const float* ln2_g = (const float*)d_in[24];
    const float* ln2_b = (const float*)d_in[25];
    const float* att_Wq = (const float*)d_in[26];
    const float* att_Wk = (const float*)d_in[27];

    float *x, *q, *k, *v, *att, *tmp, *ffn, *sk;
    cudaGetSymbolAddress((void**)&x,   g_x);
    cudaGetSymbolAddress((void**)&q,   g_q);
    cudaGetSymbolAddress((void**)&k,   g_k);
    cudaGetSymbolAddress((void**)&v,   g_v);
    cudaGetSymbolAddress((void**)&att, g_att);
    cudaGetSymbolAddress((void**)&tmp, g_tmp);
    cudaGetSymbolAddress((void**)&ffn, g_ffn);
    cudaGetSymbolAddress((void**)&sk,  g_sk);

    embed_ln_kernel<<<MM, 256>>>(input_ids, type_ids, word_emb, pos_emb,
                                 type_emb, emb_ln_g, emb_ln_b, x);

    dim3 gD(DD/128, MM/128);     // (6, 64)
    dim3 gF(FFD/128, MM/128);    // (24, 64)

    for (int l = 0; l < LL; l++) {
        const float* Wq_l = Wq + (size_t)l*DD*DD;
        const float* Wk_l = Wk + (size_t)l*DD*DD;
        const float* Wv_l = Wv + (size_t)l*DD*DD;
        const float* Wo_l = Wo + (size_t)l*DD*DD;
        const float* W1_l = W1 + (size_t)l*DD*FFD;
        const float* W2_l = W2 + (size_t)l*FFD*DD;

        gemm_kernel<1><<<gD, 256>>>(x, Wq_l, bq + l*DD, q, DD, DD);
        gemm_kernel<1><<<gD, 256>>>(x, Wk_l, bk + l*DD, k, DD, DD);
        gemm_kernel<1><<<gD, 256>>>(x, Wv_l, bv + l*DD, v, DD, DD);

        attn_kernel<<<dim3(SS, HH, BB), 256>>>(q, k, v, attn_mask, att);

        gemm_kernel<0><<<gD, 256>>>(att, Wo_l, nullptr, tmp, DD, DD);
        ln_res_kernel<<<MM, 256>>>(x, tmp, bo + l*DD, ln1_g + l*DD, ln1_b + l*DD);

        gemm_kernel<2><<<gF, 256>>>(x, W1_l, b1 + l*FFD, ffn, FFD, DD);
        gemm_kernel<0><<<gD, 256>>>(ffn, W2_l, nullptr, tmp, DD, FFD);
        ln_res_kernel<<<MM, 256>>>(x, tmp, b2 + l*DD, ln2_g + l*DD, ln2_b + l*DD);
    }

    sense_k_kernel<<<NSENSE, NATT>>>(sense_emb, att_Wk, sk);
    final_kernel<<<BB, 64>>>(x, location, att_Wq, sk, (float*)d_out);
}

// round 3
// speedup vs baseline: 4.0654x; 4.0654x over previous
#include <cuda_runtime.h>
#include <cuda_bf16.h>
#include <math.h>
#include <stdint.h>

// ---------------------------------------------------------------------------
// Problem constants
// ---------------------------------------------------------------------------
#define BB 32
#define SS 256
#define MM (BB*SS)        // 8192 rows
#define DD 768
#define HH 12
#define DHD 64
#define FFD 3072
#define LL 12
#define NSENSE 64
#define NATT 64

#define LW_QKVO ((size_t)DD*DD)
#define LW_FF   ((size_t)DD*FFD)
#define LWSTRIDE (4*LW_QKVO + 2*LW_FF)

// ---------------------------------------------------------------------------
// Scratch (static __device__ arrays; no runtime allocation allowed)
// ---------------------------------------------------------------------------
__device__ float g_x  [(size_t)MM*DD];
__device__ float g_q  [(size_t)MM*DD];
__device__ float g_k  [(size_t)MM*DD];
__device__ float g_v  [(size_t)MM*DD];
__device__ float g_att[(size_t)MM*DD];
__device__ float g_tmp[(size_t)MM*DD];
__device__ float g_ffn[(size_t)MM*FFD];
__device__ float g_sk [NSENSE*NATT];

__device__ __nv_bfloat16 g_wthi[LL*LWSTRIDE];     // transposed weights [N,K], hi
__device__ __nv_bfloat16 g_wtlo[LL*LWSTRIDE];     // transposed weights [N,K], lo
__device__ __nv_bfloat16 g_ahi [(size_t)MM*FFD];  // activation hi
__device__ __nv_bfloat16 g_alo [(size_t)MM*FFD];  // activation lo

// ---------------------------------------------------------------------------
// small asm helpers (all legal on compute_103 virtual arch: sm_80-era features)
// ---------------------------------------------------------------------------
__device__ __forceinline__ uint32_t smem_to_u32(const void* smem_ptr) {
    uint32_t addr;
    asm("{ .reg .u64 tmp; cvta.to.shared.u64 tmp, %1; cvt.u32.u64 %0, tmp; }"
        : "=r"(addr) : "l"(smem_ptr));
    return addr;
}
#define CP_ASYNC16(dst_u32, src_ptr) \
    asm volatile("cp.async.cg.shared.global [%0], [%1], 16;" \
        :: "r"(dst_u32), "l"(src_ptr))
#define CP_COMMIT asm volatile("cp.async.commit_group;" ::: "memory")
#define CP_WAIT0  asm volatile("cp.async.wait_group 0;" ::: "memory")
#define CP_WAIT1  asm volatile("cp.async.wait_group 1;" ::: "memory")

__device__ __forceinline__ void ldsm_x4(uint32_t addr, uint32_t& r0, uint32_t& r1,
                                        uint32_t& r2, uint32_t& r3) {
    asm volatile("ldmatrix.sync.aligned.m8n8.x4.shared.b16 {%0,%1,%2,%3}, [%4];"
        : "=r"(r0), "=r"(r1), "=r"(r2), "=r"(r3) : "r"(addr));
}
__device__ __forceinline__ void ldsm_x2(uint32_t addr, uint32_t& r0, uint32_t& r1) {
    asm volatile("ldmatrix.sync.aligned.m8n8.x2.shared.b16 {%0,%1}, [%2];"
        : "=r"(r0), "=r"(r1) : "r"(addr));
}
__device__ __forceinline__ void mma_bf16(float* c, const uint32_t* a, const uint32_t* b) {
    asm volatile(
        "mma.sync.aligned.m16n8k16.row.col.f32.bf16.bf16.f32 "
        "{%0,%1,%2,%3}, {%4,%5,%6,%7}, {%8,%9}, {%0,%1,%2,%3};"
        : "+f"(c[0]), "+f"(c[1]), "+f"(c[2]), "+f"(c[3])
        : "r"(a[0]), "r"(a[1]), "r"(a[2]), "r"(a[3]), "r"(b[0]), "r"(b[1]));
}

// ---------------------------------------------------------------------------
// split helpers
// ---------------------------------------------------------------------------
__device__ __forceinline__ void split2(float f, __nv_bfloat16& h, __nv_bfloat16& l) {
    h = __float2bfloat16(f);
    l = __float2bfloat16(f - __bfloat162float(h));
}

__global__ __launch_bounds__(256)
void split_kernel(const float* __restrict__ src, __nv_bfloat16* __restrict__ hi,
                  __nv_bfloat16* __restrict__ lo, int n4)
{
    int i = blockIdx.x * 256 + threadIdx.x;
    if (i >= n4) return;
    float4 v = ((const float4*)src)[i];
    __nv_bfloat16 h0,h1,h2,h3,l0,l1,l2,l3;
    split2(v.x,h0,l0); split2(v.y,h1,l1); split2(v.z,h2,l2); split2(v.w,h3,l3);
    __nv_bfloat162* hp = (__nv_bfloat162*)(hi + (size_t)i*4);
    __nv_bfloat162* lp = (__nv_bfloat162*)(lo + (size_t)i*4);
    hp[0] = __nv_bfloat162(h0,h1); hp[1] = __nv_bfloat162(h2,h3);
    lp[0] = __nv_bfloat162(l0,l1); lp[1] = __nv_bfloat162(l2,l3);
}

// transpose+split: src [K,N] fp32 -> dst hi/lo [N,K] bf16
__global__ __launch_bounds__(256)
void transpose_split_kernel(const float* __restrict__ src,
                            __nv_bfloat16* __restrict__ dhi,
                            __nv_bfloat16* __restrict__ dlo, int K, int N)
{
    __shared__ float t[32][33];
    int tx = threadIdx.x, ty = threadIdx.y;   // block (32,8)
    int nx = blockIdx.x*32 + tx;
    int ky = blockIdx.y*32;
#pragma unroll
    for (int i = 0; i < 4; i++)
        t[ty + i*8][tx] = src[(size_t)(ky + ty + i*8)*N + nx];
    __syncthreads();
    int kx = blockIdx.y*32 + tx;
    int ny = blockIdx.x*32;
#pragma unroll
    for (int i = 0; i < 4; i++) {
        float f = t[tx][ty + i*8];
        __nv_bfloat16 h, l; split2(f, h, l);
        dhi[(size_t)(ny + ty + i*8)*K + kx] = h;
        dlo[(size_t)(ny + ty + i*8)*K + kx] = l;
    }
}

// ---------------------------------------------------------------------------
// Embedding + LayerNorm
// ---------------------------------------------------------------------------
__global__ __launch_bounds__(256)
void embed_ln_kernel(const int* __restrict__ ids, const int* __restrict__ tt,
                     const float* __restrict__ we, const float* __restrict__ pe,
                     const float* __restrict__ te, const float* __restrict__ lg,
                     const float* __restrict__ lb, float* __restrict__ x)
{
    int row = blockIdx.x;
    int s   = row % SS;
    int id  = ids[row];
    int t   = tt[row];
    int tid = threadIdx.x;
    const float* wr = we + (size_t)id * DD;
    const float* pr = pe + (size_t)s  * DD;
    const float* tr = te + (size_t)t  * DD;
    float v[3]; float sum = 0.f, sq = 0.f;
#pragma unroll
    for (int i = 0; i < 3; i++) {
        int d = tid + i * 256;
        float y = wr[d] + pr[d] + tr[d];
        v[i] = y; sum += y; sq += y * y;
    }
    __shared__ float sh1[256], sh2[256];
    sh1[tid] = sum; sh2[tid] = sq;
    __syncthreads();
    for (int st = 128; st > 0; st >>= 1) {
        if (tid < st) { sh1[tid] += sh1[tid+st]; sh2[tid] += sh2[tid+st]; }
        __syncthreads();
    }
    float mu  = sh1[0] * (1.f/768.f);
    float var = fmaxf(sh2[0] * (1.f/768.f) - mu*mu, 0.f);
    float inv = rsqrtf(var + 1e-12f);
#pragma unroll
    for (int i = 0; i < 3; i++) {
        int d = tid + i * 256;
        x[(size_t)row*DD + d] = (v[i]-mu)*inv*lg[d] + lb[d];
    }
}

// ---------------------------------------------------------------------------
// Residual + bias + LayerNorm (in-place on x)
// ---------------------------------------------------------------------------
__global__ __launch_bounds__(256)
void ln_res_kernel(float* __restrict__ x, const float* __restrict__ val,
                   const float* __restrict__ bias, const float* __restrict__ lg,
                   const float* __restrict__ lb)
{
    int row = blockIdx.x;
    int tid = threadIdx.x;
    float v[3]; float sum = 0.f, sq = 0.f;
#pragma unroll
    for (int i = 0; i < 3; i++) {
        int d = tid + i * 256;
        float y = x[(size_t)row*DD + d] + val[(size_t)row*DD + d] + bias[d];
        v[i] = y; sum += y; sq += y * y;
    }
    __shared__ float sh1[256], sh2[256];
    sh1[tid] = sum; sh2[tid] = sq;
    __syncthreads();
    for (int st = 128; st > 0; st >>= 1) {
        if (tid < st) { sh1[tid] += sh1[tid+st]; sh2[tid] += sh2[tid+st]; }
        __syncthreads();
    }
    float mu  = sh1[0] * (1.f/768.f);
    float var = fmaxf(sh2[0] * (1.f/768.f) - mu*mu, 0.f);
    float inv = rsqrtf(var + 1e-12f);
#pragma unroll
    for (int i = 0; i < 3; i++) {
        int d = tid + i * 256;
        x[(size_t)row*DD + d] = (v[i]-mu)*inv*lg[d] + lb[d];
    }
}

// ---------------------------------------------------------------------------
// HMMA GEMM:  C[M,N] = A[M,K] @ Bt[N,K]^T with 3-term bf16 split (fp32-equiv).
// CTA tile 128x128x32, 8 warps (2m x 4n), warp tile 64x32, mma m16n8k16.
// 2-stage cp.async pipeline. Padded smem rows (40 elems = 80B) -> no conflicts.
// MODE 0: plain   MODE 1: +bias   MODE 2: +bias then exact gelu
// ---------------------------------------------------------------------------
__device__ __forceinline__ float gelu_exact(float x) {
    return 0.5f * x * (1.0f + erff(x * 0.70710678118654752f));
}

#define GPAD 40                  // row stride (elements) in smem tiles
#define TSZB (128*GPAD*2)        // bytes per 128x32 bf16 tile (10240)
#define STAGEB (4*TSZB)          // Ahi, Alo, Bhi, Blo  (40960)
#define GEMM_SMEM (2*STAGEB)     // 81920 bytes

__device__ __forceinline__ void gemm_load_stage(
    uint32_t sbase, const __nv_bfloat16* __restrict__ Ahi,
    const __nv_bfloat16* __restrict__ Alo, const __nv_bfloat16* __restrict__ Bhi,
    const __nv_bfloat16* __restrict__ Blo, int bm, int bn, int k0, int K, int tid)
{
    const __nv_bfloat16* bases[4] = { Ahi, Alo, Bhi, Blo };
#pragma unroll
    for (int i = 0; i < 8; i++) {
        const int tile = i >> 1;                 // 0..3 (compile-time)
        int f2 = ((i & 1) << 8) + tid;           // 0..511
        int r  = f2 >> 2;                        // 0..127
        int cq = f2 & 3;                         // 16B chunk
        int rowg = ((tile < 2) ? bm : bn) + r;
        const __nv_bfloat16* src = bases[tile] + (size_t)rowg * K + k0 + cq * 8;
        uint32_t dst = sbase + tile * TSZB + r * (GPAD*2) + cq * 16;
        CP_ASYNC16(dst, src);
    }
}

template<int MODE>
__global__ __launch_bounds__(256)
void gemm_mma(const __nv_bfloat16* __restrict__ Ahi, const __nv_bfloat16* __restrict__ Alo,
              const __nv_bfloat16* __restrict__ Bhi, const __nv_bfloat16* __restrict__ Blo,
              const float* __restrict__ bias, float* __restrict__ C, int N, int K)
{
    extern __shared__ char smem[];
    const uint32_t sb = smem_to_u32(smem);
    const int tid  = threadIdx.x;
    const int wid  = tid >> 5;
    const int lane = tid & 31;
    const int wm = wid >> 2;          // 0..1
    const int wn = wid & 3;           // 0..3
    const int bm = blockIdx.y * 128;
    const int bn = blockIdx.x * 128;

    float acc[4][4][4];
#pragma unroll
    for (int mi = 0; mi < 4; mi++)
#pragma unroll
        for (int ni = 0; ni < 4; ni++)
#pragma unroll
            for (int p = 0; p < 4; p++) acc[mi][ni][p] = 0.f;

    const int nchunks = K >> 5;

    gemm_load_stage(sb, Ahi, Alo, Bhi, Blo, bm, bn, 0, K, tid);
    CP_COMMIT;

    // per-warp ldmatrix base offsets
    const int arow = wm * 64 + (lane & 15);       // A row within tile
    const int acolh = (lane >> 4) * 8;            // A col half
    const int brow = wn * 32 + (lane & 7);        // B row within tile (n)
    const int bcolh = ((lane >> 3) & 1) * 8;      // B col half

    for (int c = 0; c < nchunks; c++) {
        if (c + 1 < nchunks) {
            gemm_load_stage(sb + ((c + 1) & 1) * STAGEB, Ahi, Alo, Bhi, Blo,
                            bm, bn, (c + 1) << 5, K, tid);
            CP_COMMIT;
            CP_WAIT1;
        } else {
            CP_WAIT0;
        }
        __syncthreads();

        const uint32_t st = sb + (c & 1) * STAGEB;
        const uint32_t aHiB = st + 0*TSZB;
        const uint32_t aLoB = st + 1*TSZB;
        const uint32_t bHiB = st + 2*TSZB;
        const uint32_t bLoB = st + 3*TSZB;

#pragma unroll
        for (int kk = 0; kk < 32; kk += 16) {
            uint32_t ah[4][4], al[4][4];
#pragma unroll
            for (int mi = 0; mi < 4; mi++) {
                uint32_t off = (uint32_t)((arow + mi*16) * (GPAD*2) + (kk + acolh) * 2);
                ldsm_x4(aHiB + off, ah[mi][0], ah[mi][1], ah[mi][2], ah[mi][3]);
                ldsm_x4(aLoB + off, al[mi][0], al[mi][1], al[mi][2], al[mi][3]);
            }
#pragma unroll
            for (int ni = 0; ni < 4; ni++) {
                uint32_t off = (uint32_t)((brow + ni*8) * (GPAD*2) + (kk + bcolh) * 2);
                uint32_t bh[2], bl[2];
                ldsm_x2(bHiB + off, bh[0], bh[1]);
                ldsm_x2(bLoB + off, bl[0], bl[1]);
#pragma unroll
                for (int mi = 0; mi < 4; mi++) {
                    mma_bf16(acc[mi][ni], ah[mi], bh);
                    mma_bf16(acc[mi][ni], ah[mi], bl);
                    mma_bf16(acc[mi][ni], al[mi], bh);
                }
            }
        }
        __syncthreads();
    }

    // epilogue: direct float2 stores
    const int qrow = lane >> 2;
    const int qcol = (lane & 3) * 2;
#pragma unroll
    for (int mi = 0; mi < 4; mi++) {
#pragma unroll
        for (int p = 0; p < 2; p++) {
            int row = bm + wm*64 + mi*16 + qrow + p*8;
#pragma unroll
            for (int ni = 0; ni < 4; ni++) {
                int col = bn + wn*32 + ni*8 + qcol;
                float v0 = acc[mi][ni][p*2 + 0];
                float v1 = acc[mi][ni][p*2 + 1];
                if (MODE >= 1) { v0 += bias[col]; v1 += bias[col+1]; }
                if (MODE == 2) { v0 = gelu_exact(v0); v1 = gelu_exact(v1); }
                float2 o; o.x = v0; o.y = v1;
                *(float2*)&C[(size_t)row * N + col] = o;
            }
        }
    }
}

// ---------------------------------------------------------------------------
// Attention: block = (32-query tile, h, b), 256 threads, dynamic smem, fp32.
// ---------------------------------------------------------------------------
#define AT_QS   0            // [32][72]
#define AT_CH   2304         // [64][72]
#define AT_S    6912         // [32][257]
#define AT_RED  15136        // [32][8]
#define AT_RMAX 15392        // [32]
#define AT_RSUM 15424        // [32]
#define AT_MB   15456        // [256]
#define AT_TOTALF 15712
#define AT_SMEM_BYTES (AT_TOTALF*4)

__global__ __launch_bounds__(256)
void attn_kernel(const float* __restrict__ q, const float* __restrict__ k,
                 const float* __restrict__ v, const int* __restrict__ mask,
                 float* __restrict__ o)
{
    extern __shared__ float sm[];
    float* Qs   = sm + AT_QS;
    float* CH   = sm + AT_CH;
    float* S    = sm + AT_S;
    float* RED  = sm + AT_RED;
    float* RMAX = sm + AT_RMAX;
    float* RSUM = sm + AT_RSUM;
    float* MB   = sm + AT_MB;

    const int qt = blockIdx.x, h = blockIdx.y, b = blockIdx.z;
    const int tid = threadIdx.x;
    const int qq = tid >> 3;       // 0..31
    const int sub = tid & 7;       // 0..7
    const int rowbase = b * SS;
    const int q0 = qt * 32;

    MB[tid] = (1.0f - (float)mask[rowbase + tid]) * -10000.0f;

#pragma unroll
    for (int i = 0; i < 8; i++) {
        int f = tid + i * 256;
        int r = f >> 6, d = f & 63;
        Qs[r * 72 + d] = q[(size_t)(rowbase + q0 + r) * DD + h * DHD + d];
    }
    __syncthreads();

    // ---- scores ----
    for (int kc = 0; kc < 4; kc++) {
#pragma unroll
        for (int i = 0; i < 16; i++) {
            int f = tid + i * 256;
            int r = f >> 6, d = f & 63;
            CH[r * 72 + d] = k[(size_t)(rowbase + kc * 64 + r) * DD + h * DHD + d];
        }
        __syncthreads();
#pragma unroll
        for (int i = 0; i < 8; i++) {
            int j = sub + i * 8;
            float s = 0.f;
#pragma unroll
            for (int d = 0; d < 64; d += 4) {
                float4 qa = *(const float4*)&Qs[qq * 72 + d];
                float4 ka = *(const float4*)&CH[j * 72 + d];
                s += qa.x * ka.x + qa.y * ka.y + qa.z * ka.z + qa.w * ka.w;
            }
            S[qq * 257 + kc * 64 + j] = s * 0.125f + MB[kc * 64 + j];
        }
        __syncthreads();
    }

    // ---- softmax ----
    {
        float m = -3.4e38f;
#pragma unroll
        for (int i = 0; i < 32; i++) m = fmaxf(m, S[qq * 257 + sub + i * 8]);
        RED[qq * 8 + sub] = m;
        __syncthreads();
        if (sub == 0) {
            float mm = RED[qq * 8];
#pragma unroll
            for (int i = 1; i < 8; i++) mm = fmaxf(mm, RED[qq * 8 + i]);
            RMAX[qq] = mm;
        }
        __syncthreads();
        float mx = RMAX[qq];
        float ssum = 0.f;
#pragma unroll
        for (int i = 0; i < 32; i++) {
            int idx = qq * 257 + sub + i * 8;
            float e = __expf(S[idx] - mx);
            S[idx] = e;
            ssum += e;
        }
        RED[qq * 8 + sub] = ssum;
        __syncthreads();
        if (sub == 0) {
            float t = 0.f;
#pragma unroll
            for (int i = 0; i < 8; i++) t += RED[qq * 8 + i];
            RSUM[qq] = t;
        }
        __syncthreads();
    }

    // ---- O = P @ V ----
    float acc[8];
#pragma unroll
    for (int m2 = 0; m2 < 8; m2++) acc[m2] = 0.f;
    const int d0 = sub * 8;
    for (int vc = 0; vc < 4; vc++) {
        __syncthreads();
#pragma unroll
        for (int i = 0; i < 16; i++) {
            int f = tid + i * 256;
            int r = f >> 6, d = f & 63;
            CH[r * 72 + d] = v[(size_t)(rowbase + vc * 64 + r) * DD + h * DHD + d];
        }
        __syncthreads();
#pragma unroll 4
        for (int j = 0; j < 64; j++) {
            float p = S[qq * 257 + vc * 64 + j];
            float4 va = *(const float4*)&CH[j * 72 + d0];
            float4 vb = *(const float4*)&CH[j * 72 + d0 + 4];
            acc[0] += p * va.x; acc[1] += p * va.y;
            acc[2] += p * va.z; acc[3] += p * va.w;
            acc[4] += p * vb.x; acc[5] += p * vb.y;
            acc[6] += p * vb.z; acc[7] += p * vb.w;
        }
    }
    float inv = 1.0f / RSUM[qq];
    float* op = &o[(size_t)(rowbase + q0 + qq) * DD + h * DHD + d0];
#pragma unroll
    for (int m2 = 0; m2 < 8; m2++) op[m2] = acc[m2] * inv;
}

// ---------------------------------------------------------------------------
// sense key projection + final top-2
// ---------------------------------------------------------------------------
__global__ __launch_bounds__(64)
void sense_k_kernel(const float* __restrict__ sense, const float* __restrict__ Wk,
                    float* __restrict__ sk)
{
    int j = blockIdx.x, t = threadIdx.x;
    float s = 0.f;
    for (int d = 0; d < DD; d++)
        s += sense[(size_t)j*DD + d] * Wk[(size_t)d*NATT + t];
    sk[j*NATT + t] = s;
}

__global__ __launch_bounds__(64)
void final_kernel(const float* __restrict__ x, const int* __restrict__ loc,
                  const float* __restrict__ Wq, const float* __restrict__ sk,
                  float* __restrict__ out)
{
    int b = blockIdx.x, t = threadIdx.x;
    __shared__ float pun[DD];
    __shared__ float pq[NATT];
    __shared__ float sc[NSENSE];

    int r = b*SS + loc[b];
    for (int d = t; d < DD; d += 64) pun[d] = x[(size_t)r*DD + d];
    __syncthreads();

    float s = 0.f;
    for (int d = 0; d < DD; d++) s += pun[d] * Wq[(size_t)d*NATT + t];
    pq[t] = s;
    __syncthreads();

    float sv = 0.f;
#pragma unroll
    for (int u = 0; u < NATT; u++) sv += pq[u] * sk[t*NATT + u];
    sc[t] = sv * 0.125f;
    __syncthreads();

    if (t == 0) {
        int i1 = 0; float b1v = sc[0];
        for (int i = 1; i < NSENSE; i++) if (sc[i] > b1v) { b1v = sc[i]; i1 = i; }
        int i2 = -1; float b2v = -3.4e38f;
        for (int i = 0; i < NSENSE; i++) if (i != i1 && sc[i] > b2v) { b2v = sc[i]; i2 = i; }
        out[b*2+0] = (float)i1;
        out[b*2+1] = (float)i2;
    }
}

// ---------------------------------------------------------------------------
// launch
// ---------------------------------------------------------------------------
static void split_launch(const float* src, __nv_bfloat16* hi, __nv_bfloat16* lo, size_t n)
{
    int n4 = (int)(n / 4);
    split_kernel<<<(n4 + 255) / 256, 256>>>(src, hi, lo, n4);
}

extern "C" void kernel_launch(void* const* d_in, const int* in_sizes, int n_in,
                              void* d_out, int out_size)
{
    const int*   input_ids = (const int*)  d_in[0];
    const int*   type_ids  = (const int*)  d_in[1];
    const int*   attn_mask = (const int*)  d_in[2];
    const int*   location  = (const int*)  d_in[3];
    const float* sense_emb = (const float*)d_in[4];
    const float* word_emb  = (const float*)d_in[5];
    const float* pos_emb   = (const float*)d_in[6];
    const float* type_emb  = (const float*)d_in[7];
    const float* emb_ln_g  = (const float*)d_in[8];
    const float* emb_ln_b  = (const float*)d_in[9];
    const float* Wq = (const float*)d_in[10];
    const float* bq = (const float*)d_in[11];
    const float* Wk = (const float*)d_in[12];
    const float* bk = (const float*)d_in[13];
    const float* Wv = (const float*)d_in[14];
    const float* bv = (const float*)d_in[15];
    const float* Wo = (const float*)d_in[16];
    const float* bo = (const float*)d_in[17];
    const float* ln1_g = (const float*)d_in[18];
    const float* ln1_b = (const float*)d_in[19];
    const float* W1 = (const float*)d_in[20];
    const float* b1 = (const float*)d_in[21];
    const float* W2 = (const float*)d_in[22];
    const float* b2 = (const float*)d_in[23];
    const float* ln2_g = (const float*)d_in[24];
    const float* ln2_b = (const float*)d_in[25];
    const float* att_Wq = (const float*)d_in[26];
    const float* att_Wk = (const float*)d_in[27];

    float *x, *q, *k, *v, *att, *tmp, *ffn, *sk;
    __nv_bfloat16 *wthi, *wtlo, *ahi, *alo;
    cudaGetSymbolAddress((void**)&x,    g_x);
    cudaGetSymbolAddress((void**)&q,    g_q);
    cudaGetSymbolAddress((void**)&k,    g_k);
    cudaGetSymbolAddress((void**)&v,    g_v);
    cudaGetSymbolAddress((void**)&att,  g_att);
    cudaGetSymbolAddress((void**)&tmp,  g_tmp);
    cudaGetSymbolAddress((void**)&ffn,  g_ffn);
    cudaGetSymbolAddress((void**)&sk,   g_sk);
    cudaGetSymbolAddress((void**)&wthi, g_wthi);
    cudaGetSymbolAddress((void**)&wtlo, g_wtlo);
    cudaGetSymbolAddress((void**)&ahi,  g_ahi);
    cudaGetSymbolAddress((void**)&alo,  g_alo);

    cudaFuncSetAttribute(gemm_mma<0>, cudaFuncAttributeMaxDynamicSharedMemorySize, GEMM_SMEM);
    cudaFuncSetAttribute(gemm_mma<1>, cudaFuncAttributeMaxDynamicSharedMemorySize, GEMM_SMEM);
    cudaFuncSetAttribute(gemm_mma<2>, cudaFuncAttributeMaxDynamicSharedMemorySize, GEMM_SMEM);
    cudaFuncSetAttribute(attn_kernel, cudaFuncAttributeMaxDynamicSharedMemorySize, AT_SMEM_BYTES);

    // ---- weight prep: transpose + split all layer weights ----
    dim3 tb(32, 8);
    for (int l = 0; l < LL; l++) {
        size_t base = (size_t)l * LWSTRIDE;
        const float* srcs[4] = { Wq + (size_t)l*DD*DD, Wk + (size_t)l*DD*DD,
                                 Wv + (size_t)l*DD*DD, Wo + (size_t)l*DD*DD };
        for (int m2 = 0; m2 < 4; m2++) {
            size_t off = base + (size_t)m2 * LW_QKVO;
            transpose_split_kernel<<<dim3(DD/32, DD/32), tb>>>(srcs[m2], wthi + off, wtlo + off, DD, DD);
        }
        transpose_split_kernel<<<dim3(FFD/32, DD/32), tb>>>(W1 + (size_t)l*DD*FFD,
            wthi + base + 4*LW_QKVO, wtlo + base + 4*LW_QKVO, DD, FFD);
        transpose_split_kernel<<<dim3(DD/32, FFD/32), tb>>>(W2 + (size_t)l*FFD*DD,
            wthi + base + 4*LW_QKVO + LW_FF, wtlo + base + 4*LW_QKVO + LW_FF, FFD, DD);
    }

    embed_ln_kernel<<<MM, 256>>>(input_ids, type_ids, word_emb, pos_emb,
                                 type_emb, emb_ln_g, emb_ln_b, x);

    dim3 gD(DD/128, MM/128);      // (6, 64)
    dim3 gF(FFD/128, MM/128);     // (24, 64)

    for (int l = 0; l < LL; l++) {
        size_t base = (size_t)l * LWSTRIDE;
        const __nv_bfloat16* wq_h = wthi + base;              const __nv_bfloat16* wq_l = wtlo + base;
        const __nv_bfloat16* wk_h = wthi + base + LW_QKVO;    const __nv_bfloat16* wk_l = wtlo + base + LW_QKVO;
        const __nv_bfloat16* wv_h = wthi + base + 2*LW_QKVO;  const __nv_bfloat16* wv_l = wtlo + base + 2*LW_QKVO;
        const __nv_bfloat16* wo_h = wthi + base + 3*LW_QKVO;  const __nv_bfloat16* wo_l = wtlo + base + 3*LW_QKVO;
        const __nv_bfloat16* w1_h = wthi + base + 4*LW_QKVO;  const __nv_bfloat16* w1_l = wtlo + base + 4*LW_QKVO;
        const __nv_bfloat16* w2_h = wthi + base + 4*LW_QKVO + LW_FF;
        const __nv_bfloat16* w2_l = wtlo + base + 4*LW_QKVO + LW_FF;

        split_launch(x, ahi, alo, (size_t)MM*DD);
        gemm_mma<1><<<gD, 256, GEMM_SMEM>>>(ahi, alo, wq_h, wq_l, bq + l*DD, q, DD, DD);
        gemm_mma<1><<<gD, 256, GEMM_SMEM>>>(ahi, alo, wk_h, wk_l, bk + l*DD, k, DD, DD);
        gemm_mma<1><<<gD, 256, GEMM_SMEM>>>(ahi, alo, wv_h, wv_l, bv + l*DD, v, DD, DD);

        attn_kernel<<<dim3(SS/32, HH, BB), 256, AT_SMEM_BYTES>>>(q, k, v, attn_mask, att);

        split_launch(att, ahi, alo, (size_t)MM*DD);
        gemm_mma<0><<<gD, 256, GEMM_SMEM>>>(ahi, alo, wo_h, wo_l, nullptr, tmp, DD, DD);
        ln_res_kernel<<<MM, 256>>>(x, tmp, bo + l*DD, ln1_g + l*DD, ln1_b + l*DD);

        split_launch(x, ahi, alo, (size_t)MM*DD);
        gemm_mma<2><<<gF, 256, GEMM_SMEM>>>(ahi, alo, w1_h, w1_l, b1 + l*FFD, ffn, FFD, DD);
        split_launch(ffn, ahi, alo, (size_t)MM*FFD);
        gemm_mma<0><<<gD, 256, GEMM_SMEM>>>(ahi, alo, w2_h, w2_l, nullptr, tmp, DD, FFD);
        ln_res_kernel<<<MM, 256>>>(x, tmp, b2 + l*DD, ln2_g + l*DD, ln2_b + l*DD);
    }

    sense_k_kernel<<<NSENSE, NATT>>>(sense_emb, att_Wk, sk);
    final_kernel<<<BB, 64>>>(x, location, att_Wq, sk, (float*)d_out);
}

// round 4
// speedup vs baseline: 4.1857x; 1.0296x over previous
#include <cuda_runtime.h>
#include <cuda_bf16.h>
#include <math.h>
#include <stdint.h>

// ---------------------------------------------------------------------------
// Problem constants
// ---------------------------------------------------------------------------
#define BB 32
#define SS 256
#define MM (BB*SS)        // 8192 rows
#define DD 768
#define HH 12
#define DHD 64
#define FFD 3072
#define LL 12
#define NSENSE 64
#define NATT 64
#define QKVN (3*DD)       // 2304

#define LW_QKVO ((size_t)DD*DD)
#define LW_FF   ((size_t)DD*FFD)
#define LWSTRIDE (4*LW_QKVO + 2*LW_FF)

// ---------------------------------------------------------------------------
// Scratch (static __device__ arrays; no runtime allocation allowed)
// ---------------------------------------------------------------------------
__device__ float g_x  [(size_t)MM*DD];         // residual stream (fp32)
__device__ float g_qkv[(size_t)MM*QKVN];       // fused QKV output (fp32)
__device__ float g_tmp[(size_t)MM*DD];         // gemm output before LN
__device__ float g_sk [NSENSE*NATT];
__device__ float g_cbias[LL*QKVN];             // concatenated qkv bias

__device__ __nv_bfloat16 g_wthi[LL*LWSTRIDE];     // transposed weights [N,K], hi
__device__ __nv_bfloat16 g_wtlo[LL*LWSTRIDE];     // transposed weights [N,K], lo
__device__ __nv_bfloat16 g_ahi [(size_t)MM*DD];   // activation hi (D-wide)
__device__ __nv_bfloat16 g_alo [(size_t)MM*DD];   // activation lo
__device__ __nv_bfloat16 g_bhi [(size_t)MM*FFD];  // ffn hidden hi
__device__ __nv_bfloat16 g_blo [(size_t)MM*FFD];  // ffn hidden lo

// ---------------------------------------------------------------------------
// asm helpers (sm_80-era features, legal on compute_103)
// ---------------------------------------------------------------------------
__device__ __forceinline__ uint32_t smem_to_u32(const void* smem_ptr) {
    uint32_t addr;
    asm("{ .reg .u64 tmp; cvta.to.shared.u64 tmp, %1; cvt.u32.u64 %0, tmp; }"
        : "=r"(addr) : "l"(smem_ptr));
    return addr;
}
#define CP_ASYNC16(dst_u32, src_ptr) \
    asm volatile("cp.async.cg.shared.global [%0], [%1], 16;" \
        :: "r"(dst_u32), "l"(src_ptr))
#define CP_COMMIT asm volatile("cp.async.commit_group;" ::: "memory")
#define CP_WAIT0  asm volatile("cp.async.wait_group 0;" ::: "memory")
#define CP_WAIT1  asm volatile("cp.async.wait_group 1;" ::: "memory")

__device__ __forceinline__ void ldsm_x4(uint32_t addr, uint32_t& r0, uint32_t& r1,
                                        uint32_t& r2, uint32_t& r3) {
    asm volatile("ldmatrix.sync.aligned.m8n8.x4.shared.b16 {%0,%1,%2,%3}, [%4];"
        : "=r"(r0), "=r"(r1), "=r"(r2), "=r"(r3) : "r"(addr));
}
__device__ __forceinline__ void ldsm_x2(uint32_t addr, uint32_t& r0, uint32_t& r1) {
    asm volatile("ldmatrix.sync.aligned.m8n8.x2.shared.b16 {%0,%1}, [%2];"
        : "=r"(r0), "=r"(r1) : "r"(addr));
}
__device__ __forceinline__ void mma_bf16(float* c, const uint32_t* a, const uint32_t* b) {
    asm volatile(
        "mma.sync.aligned.m16n8k16.row.col.f32.bf16.bf16.f32 "
        "{%0,%1,%2,%3}, {%4,%5,%6,%7}, {%8,%9}, {%0,%1,%2,%3};"
        : "+f"(c[0]), "+f"(c[1]), "+f"(c[2]), "+f"(c[3])
        : "r"(a[0]), "r"(a[1]), "r"(a[2]), "r"(a[3]), "r"(b[0]), "r"(b[1]));
}

__device__ __forceinline__ void split2(float f, __nv_bfloat16& h, __nv_bfloat16& l) {
    h = __float2bfloat16(f);
    l = __float2bfloat16(f - __bfloat162float(h));
}

// ---------------------------------------------------------------------------
// weight prep: transpose+split [K,N] fp32 -> [N,K] bf16 hi/lo
// ---------------------------------------------------------------------------
__global__ __launch_bounds__(256)
void transpose_split_kernel(const float* __restrict__ src,
                            __nv_bfloat16* __restrict__ dhi,
                            __nv_bfloat16* __restrict__ dlo, int K, int N)
{
    __shared__ float t[32][33];
    int tx = threadIdx.x, ty = threadIdx.y;   // block (32,8)
    int nx = blockIdx.x*32 + tx;
    int ky = blockIdx.y*32;
#pragma unroll
    for (int i = 0; i < 4; i++)
        t[ty + i*8][tx] = src[(size_t)(ky + ty + i*8)*N + nx];
    __syncthreads();
    int kx = blockIdx.y*32 + tx;
    int ny = blockIdx.x*32;
#pragma unroll
    for (int i = 0; i < 4; i++) {
        float f = t[tx][ty + i*8];
        __nv_bfloat16 h, l; split2(f, h, l);
        dhi[(size_t)(ny + ty + i*8)*K + kx] = h;
        dlo[(size_t)(ny + ty + i*8)*K + kx] = l;
    }
}

__global__ __launch_bounds__(256)
void concat_bias_kernel(const float* __restrict__ bq, const float* __restrict__ bk,
                        const float* __restrict__ bv, float* __restrict__ cb)
{
    int idx = blockIdx.x * 256 + threadIdx.x;
    if (idx >= LL * QKVN) return;
    int l = idx / QKVN, j = idx % QKVN;
    float v;
    if (j < DD)            v = bq[l*DD + j];
    else if (j < 2*DD)     v = bk[l*DD + j - DD];
    else                   v = bv[l*DD + j - 2*DD];
    cb[idx] = v;
}

// ---------------------------------------------------------------------------
// Embedding + LayerNorm -> x fp32 + (hi,lo) bf16 split
// ---------------------------------------------------------------------------
__global__ __launch_bounds__(256)
void embed_ln_kernel(const int* __restrict__ ids, const int* __restrict__ tt,
                     const float* __restrict__ we, const float* __restrict__ pe,
                     const float* __restrict__ te, const float* __restrict__ lg,
                     const float* __restrict__ lb, float* __restrict__ x,
                     __nv_bfloat16* __restrict__ xhi, __nv_bfloat16* __restrict__ xlo)
{
    int row = blockIdx.x;
    int s   = row % SS;
    int id  = ids[row];
    int t   = tt[row];
    int tid = threadIdx.x;
    const float* wr = we + (size_t)id * DD;
    const float* pr = pe + (size_t)s  * DD;
    const float* tr = te + (size_t)t  * DD;
    float v[3]; float sum = 0.f, sq = 0.f;
#pragma unroll
    for (int i = 0; i < 3; i++) {
        int d = tid + i * 256;
        float y = wr[d] + pr[d] + tr[d];
        v[i] = y; sum += y; sq += y * y;
    }
    __shared__ float sh1[256], sh2[256];
    sh1[tid] = sum; sh2[tid] = sq;
    __syncthreads();
    for (int st = 128; st > 0; st >>= 1) {
        if (tid < st) { sh1[tid] += sh1[tid+st]; sh2[tid] += sh2[tid+st]; }
        __syncthreads();
    }
    float mu  = sh1[0] * (1.f/768.f);
    float var = fmaxf(sh2[0] * (1.f/768.f) - mu*mu, 0.f);
    float inv = rsqrtf(var + 1e-12f);
#pragma unroll
    for (int i = 0; i < 3; i++) {
        int d = tid + i * 256;
        float y = (v[i]-mu)*inv*lg[d] + lb[d];
        size_t o = (size_t)row*DD + d;
        x[o] = y;
        __nv_bfloat16 h, l; split2(y, h, l);
        xhi[o] = h; xlo[o] = l;
    }
}

// ---------------------------------------------------------------------------
// Residual + bias + LayerNorm -> x fp32 (in place) + split
// ---------------------------------------------------------------------------
__global__ __launch_bounds__(256)
void ln_res_kernel(float* __restrict__ x, const float* __restrict__ val,
                   const float* __restrict__ bias, const float* __restrict__ lg,
                   const float* __restrict__ lb,
                   __nv_bfloat16* __restrict__ xhi, __nv_bfloat16* __restrict__ xlo)
{
    int row = blockIdx.x;
    int tid = threadIdx.x;
    float v[3]; float sum = 0.f, sq = 0.f;
#pragma unroll
    for (int i = 0; i < 3; i++) {
        int d = tid + i * 256;
        float y = x[(size_t)row*DD + d] + val[(size_t)row*DD + d] + bias[d];
        v[i] = y; sum += y; sq += y * y;
    }
    __shared__ float sh1[256], sh2[256];
    sh1[tid] = sum; sh2[tid] = sq;
    __syncthreads();
    for (int st = 128; st > 0; st >>= 1) {
        if (tid < st) { sh1[tid] += sh1[tid+st]; sh2[tid] += sh2[tid+st]; }
        __syncthreads();
    }
    float mu  = sh1[0] * (1.f/768.f);
    float var = fmaxf(sh2[0] * (1.f/768.f) - mu*mu, 0.f);
    float inv = rsqrtf(var + 1e-12f);
#pragma unroll
    for (int i = 0; i < 3; i++) {
        int d = tid + i * 256;
        float y = (v[i]-mu)*inv*lg[d] + lb[d];
        size_t o = (size_t)row*DD + d;
        x[o] = y;
        __nv_bfloat16 h, l; split2(y, h, l);
        xhi[o] = h; xlo[o] = l;
    }
}

// ---------------------------------------------------------------------------
// HMMA GEMM: C[M,N] = A[M,K] @ Bt[N,K]^T, 3-term bf16 split, fp32-equivalent.
// CTA 128x128x32, 8 warps (2m x 4n), mma m16n8k16, 3-stage cp.async pipeline.
// MODE 0: C fp32            MODE 1: C fp32 + bias
// MODE 2: bias + gelu -> split bf16 outputs (Chi, Clo)
// ---------------------------------------------------------------------------
__device__ __forceinline__ float gelu_exact(float x) {
    return 0.5f * x * (1.0f + erff(x * 0.70710678118654752f));
}

#define GPAD 40                  // smem row stride (elements)
#define TSZB (128*GPAD*2)        // 10240 B per 128x32 bf16 tile
#define STAGEB (4*TSZB)          // Ahi, Alo, Bhi, Blo  (40960 B)
#define NSTAGE 3
#define GEMM_SMEM (NSTAGE*STAGEB)   // 122880 B

__device__ __forceinline__ void gemm_load_stage(
    uint32_t sbase, const __nv_bfloat16* __restrict__ Ahi,
    const __nv_bfloat16* __restrict__ Alo, const __nv_bfloat16* __restrict__ Bhi,
    const __nv_bfloat16* __restrict__ Blo, int bm, int bn, int k0, int K, int tid)
{
    const __nv_bfloat16* bases[4] = { Ahi, Alo, Bhi, Blo };
#pragma unroll
    for (int i = 0; i < 8; i++) {
        const int tile = i >> 1;                 // 0..3
        int f2 = ((i & 1) << 8) + tid;           // 0..511
        int r  = f2 >> 2;                        // 0..127
        int cq = f2 & 3;                         // 16B chunk
        int rowg = ((tile < 2) ? bm : bn) + r;
        const __nv_bfloat16* src = bases[tile] + (size_t)rowg * K + k0 + cq * 8;
        uint32_t dst = sbase + tile * TSZB + r * (GPAD*2) + cq * 16;
        CP_ASYNC16(dst, src);
    }
}

template<int MODE>
__global__ __launch_bounds__(256)
void gemm_mma(const __nv_bfloat16* __restrict__ Ahi, const __nv_bfloat16* __restrict__ Alo,
              const __nv_bfloat16* __restrict__ Bhi, const __nv_bfloat16* __restrict__ Blo,
              const float* __restrict__ bias, float* __restrict__ C,
              __nv_bfloat16* __restrict__ Chi, __nv_bfloat16* __restrict__ Clo,
              int N, int K)
{
    extern __shared__ char smem[];
    const uint32_t sb = smem_to_u32(smem);
    const int tid  = threadIdx.x;
    const int wid  = tid >> 5;
    const int lane = tid & 31;
    const int wm = wid >> 2;          // 0..1
    const int wn = wid & 3;           // 0..3
    const int bm = blockIdx.y * 128;
    const int bn = blockIdx.x * 128;

    float acc[4][4][4];
#pragma unroll
    for (int mi = 0; mi < 4; mi++)
#pragma unroll
        for (int ni = 0; ni < 4; ni++)
#pragma unroll
            for (int p = 0; p < 4; p++) acc[mi][ni][p] = 0.f;

    const int nchunks = K >> 5;

    gemm_load_stage(sb, Ahi, Alo, Bhi, Blo, bm, bn, 0, K, tid);
    CP_COMMIT;
    gemm_load_stage(sb + STAGEB, Ahi, Alo, Bhi, Blo, bm, bn, 32, K, tid);
    CP_COMMIT;

    const int arow = wm * 64 + (lane & 15);
    const int acolh = (lane >> 4) * 8;
    const int brow = wn * 32 + (lane & 7);
    const int bcolh = ((lane >> 3) & 1) * 8;

    for (int c = 0; c < nchunks; c++) {
        if (c + 1 < nchunks) { CP_WAIT1; } else { CP_WAIT0; }
        __syncthreads();
        if (c + 2 < nchunks) {
            int s2 = (c + 2) % NSTAGE;
            gemm_load_stage(sb + s2 * STAGEB, Ahi, Alo, Bhi, Blo, bm, bn,
                            (c + 2) << 5, K, tid);
            CP_COMMIT;
        }

        const uint32_t st = sb + (c % NSTAGE) * STAGEB;
        const uint32_t aHiB = st + 0*TSZB;
        const uint32_t aLoB = st + 1*TSZB;
        const uint32_t bHiB = st + 2*TSZB;
        const uint32_t bLoB = st + 3*TSZB;

#pragma unroll
        for (int kk = 0; kk < 32; kk += 16) {
            uint32_t ah[4][4], al[4][4];
#pragma unroll
            for (int mi = 0; mi < 4; mi++) {
                uint32_t off = (uint32_t)((arow + mi*16) * (GPAD*2) + (kk + acolh) * 2);
                ldsm_x4(aHiB + off, ah[mi][0], ah[mi][1], ah[mi][2], ah[mi][3]);
                ldsm_x4(aLoB + off, al[mi][0], al[mi][1], al[mi][2], al[mi][3]);
            }
#pragma unroll
            for (int ni = 0; ni < 4; ni++) {
                uint32_t off = (uint32_t)((brow + ni*8) * (GPAD*2) + (kk + bcolh) * 2);
                uint32_t bh[2], bl[2];
                ldsm_x2(bHiB + off, bh[0], bh[1]);
                ldsm_x2(bLoB + off, bl[0], bl[1]);
#pragma unroll
                for (int mi = 0; mi < 4; mi++) {
                    mma_bf16(acc[mi][ni], ah[mi], bh);
                    mma_bf16(acc[mi][ni], ah[mi], bl);
                    mma_bf16(acc[mi][ni], al[mi], bh);
                }
            }
        }
    }

    // epilogue
    const int qrow = lane >> 2;
    const int qcol = (lane & 3) * 2;
#pragma unroll
    for (int mi = 0; mi < 4; mi++) {
#pragma unroll
        for (int p = 0; p < 2; p++) {
            int row = bm + wm*64 + mi*16 + qrow + p*8;
#pragma unroll
            for (int ni = 0; ni < 4; ni++) {
                int col = bn + wn*32 + ni*8 + qcol;
                float v0 = acc[mi][ni][p*2 + 0];
                float v1 = acc[mi][ni][p*2 + 1];
                if (MODE >= 1) { v0 += bias[col]; v1 += bias[col+1]; }
                if (MODE == 2) {
                    v0 = gelu_exact(v0); v1 = gelu_exact(v1);
                    __nv_bfloat16 h0,l0,h1,l1;
                    split2(v0,h0,l0); split2(v1,h1,l1);
                    *(__nv_bfloat162*)&Chi[(size_t)row * N + col] = __nv_bfloat162(h0,h1);
                    *(__nv_bfloat162*)&Clo[(size_t)row * N + col] = __nv_bfloat162(l0,l1);
                } else {
                    float2 o; o.x = v0; o.y = v1;
                    *(float2*)&C[(size_t)row * N + col] = o;
                }
            }
        }
    }
}

// ---------------------------------------------------------------------------
// Attention: block = (32-query tile, h, b), 256 threads, fp32, reads fused qkv,
// writes output pre-split as bf16 hi/lo [M, D].
// ---------------------------------------------------------------------------
#define AT_QS   0            // [32][72]
#define AT_CH   2304         // [64][72]
#define AT_S    6912         // [32][257]
#define AT_RED  15136        // [32][8]
#define AT_RMAX 15392        // [32]
#define AT_RSUM 15424        // [32]
#define AT_MB   15456        // [256]
#define AT_TOTALF 15712
#define AT_SMEM_BYTES (AT_TOTALF*4)

__global__ __launch_bounds__(256)
void attn_kernel(const float* __restrict__ qkv, const int* __restrict__ mask,
                 __nv_bfloat16* __restrict__ ohi, __nv_bfloat16* __restrict__ olo)
{
    extern __shared__ float sm[];
    float* Qs   = sm + AT_QS;
    float* CH   = sm + AT_CH;
    float* S    = sm + AT_S;
    float* RED  = sm + AT_RED;
    float* RMAX = sm + AT_RMAX;
    float* RSUM = sm + AT_RSUM;
    float* MB   = sm + AT_MB;

    const int qt = blockIdx.x, h = blockIdx.y, b = blockIdx.z;
    const int tid = threadIdx.x;
    const int qq = tid >> 3;       // 0..31
    const int sub = tid & 7;       // 0..7
    const int rowbase = b * SS;
    const int q0 = qt * 32;
    const int hoff = h * DHD;

    MB[tid] = (1.0f - (float)mask[rowbase + tid]) * -10000.0f;

#pragma unroll
    for (int i = 0; i < 8; i++) {
        int f = tid + i * 256;
        int r = f >> 6, d = f & 63;
        Qs[r * 72 + d] = qkv[(size_t)(rowbase + q0 + r) * QKVN + hoff + d];
    }
    __syncthreads();

    // ---- scores (K at offset +DD in qkv) ----
    for (int kc = 0; kc < 4; kc++) {
#pragma unroll
        for (int i = 0; i < 16; i++) {
            int f = tid + i * 256;
            int r = f >> 6, d = f & 63;
            CH[r * 72 + d] = qkv[(size_t)(rowbase + kc * 64 + r) * QKVN + DD + hoff + d];
        }
        __syncthreads();
#pragma unroll
        for (int i = 0; i < 8; i++) {
            int j = sub + i * 8;
            float s = 0.f;
#pragma unroll
            for (int d = 0; d < 64; d += 4) {
                float4 qa = *(const float4*)&Qs[qq * 72 + d];
                float4 ka = *(const float4*)&CH[j * 72 + d];
                s += qa.x * ka.x + qa.y * ka.y + qa.z * ka.z + qa.w * ka.w;
            }
            S[qq * 257 + kc * 64 + j] = s * 0.125f + MB[kc * 64 + j];
        }
        __syncthreads();
    }

    // ---- softmax ----
    {
        float m = -3.4e38f;
#pragma unroll
        for (int i = 0; i < 32; i++) m = fmaxf(m, S[qq * 257 + sub + i * 8]);
        RED[qq * 8 + sub] = m;
        __syncthreads();
        if (sub == 0) {
            float mm = RED[qq * 8];
#pragma unroll
            for (int i = 1; i < 8; i++) mm = fmaxf(mm, RED[qq * 8 + i]);
            RMAX[qq] = mm;
        }
        __syncthreads();
        float mx = RMAX[qq];
        float ssum = 0.f;
#pragma unroll
        for (int i = 0; i < 32; i++) {
            int idx = qq * 257 + sub + i * 8;
            float e = __expf(S[idx] - mx);
            S[idx] = e;
            ssum += e;
        }
        RED[qq * 8 + sub] = ssum;
        __syncthreads();
        if (sub == 0) {
            float t = 0.f;
#pragma unroll
            for (int i = 0; i < 8; i++) t += RED[qq * 8 + i];
            RSUM[qq] = t;
        }
        __syncthreads();
    }

    // ---- O = P @ V  (V at offset +2*DD) ----
    float acc[8];
#pragma unroll
    for (int m2 = 0; m2 < 8; m2++) acc[m2] = 0.f;
    const int d0 = sub * 8;
    for (int vc = 0; vc < 4; vc++) {
        __syncthreads();
#pragma unroll
        for (int i = 0; i < 16; i++) {
            int f = tid + i * 256;
            int r = f >> 6, d = f & 63;
            CH[r * 72 + d] = qkv[(size_t)(rowbase + vc * 64 + r) * QKVN + 2*DD + hoff + d];
        }
        __syncthreads();
#pragma unroll 4
        for (int j = 0; j < 64; j++) {
            float p = S[qq * 257 + vc * 64 + j];
            float4 va = *(const float4*)&CH[j * 72 + d0];
            float4 vb = *(const float4*)&CH[j * 72 + d0 + 4];
            acc[0] += p * va.x; acc[1] += p * va.y;
            acc[2] += p * va.z; acc[3] += p * va.w;
            acc[4] += p * vb.x; acc[5] += p * vb.y;
            acc[6] += p * vb.z; acc[7] += p * vb.w;
        }
    }
    float inv = 1.0f / RSUM[qq];
    size_t obase = (size_t)(rowbase + q0 + qq) * DD + hoff + d0;
#pragma unroll
    for (int m2 = 0; m2 < 8; m2 += 2) {
        float y0 = acc[m2] * inv, y1 = acc[m2+1] * inv;
        __nv_bfloat16 h0,l0,h1,l1;
        split2(y0,h0,l0); split2(y1,h1,l1);
        *(__nv_bfloat162*)&ohi[obase + m2] = __nv_bfloat162(h0,h1);
        *(__nv_bfloat162*)&olo[obase + m2] = __nv_bfloat162(l0,l1);
    }
}

// ---------------------------------------------------------------------------
// sense key projection + final top-2
// ---------------------------------------------------------------------------
__global__ __launch_bounds__(64)
void sense_k_kernel(const float* __restrict__ sense, const float* __restrict__ Wk,
                    float* __restrict__ sk)
{
    int j = blockIdx.x, t = threadIdx.x;
    float s = 0.f;
    for (int d = 0; d < DD; d++)
        s += sense[(size_t)j*DD + d] * Wk[(size_t)d*NATT + t];
    sk[j*NATT + t] = s;
}

__global__ __launch_bounds__(64)
void final_kernel(const float* __restrict__ x, const int* __restrict__ loc,
                  const float* __restrict__ Wq, const float* __restrict__ sk,
                  float* __restrict__ out)
{
    int b = blockIdx.x, t = threadIdx.x;
    __shared__ float pun[DD];
    __shared__ float pq[NATT];
    __shared__ float sc[NSENSE];

    int r = b*SS + loc[b];
    for (int d = t; d < DD; d += 64) pun[d] = x[(size_t)r*DD + d];
    __syncthreads();

    float s = 0.f;
    for (int d = 0; d < DD; d++) s += pun[d] * Wq[(size_t)d*NATT + t];
    pq[t] = s;
    __syncthreads();

    float sv = 0.f;
#pragma unroll
    for (int u = 0; u < NATT; u++) sv += pq[u] * sk[t*NATT + u];
    sc[t] = sv * 0.125f;
    __syncthreads();

    if (t == 0) {
        int i1 = 0; float b1v = sc[0];
        for (int i = 1; i < NSENSE; i++) if (sc[i] > b1v) { b1v = sc[i]; i1 = i; }
        int i2 = -1; float b2v = -3.4e38f;
        for (int i = 0; i < NSENSE; i++) if (i != i1 && sc[i] > b2v) { b2v = sc[i]; i2 = i; }
        out[b*2+0] = (float)i1;
        out[b*2+1] = (float)i2;
    }
}

// ---------------------------------------------------------------------------
// launch
// ---------------------------------------------------------------------------
extern "C" void kernel_launch(void* const* d_in, const int* in_sizes, int n_in,
                              void* d_out, int out_size)
{
    const int*   input_ids = (const int*)  d_in[0];
    const int*   type_ids  = (const int*)  d_in[1];
    const int*   attn_mask = (const int*)  d_in[2];
    const int*   location  = (const int*)  d_in[3];
    const float* sense_emb = (const float*)d_in[4];
    const float* word_emb  = (const float*)d_in[5];
    const float* pos_emb   = (const float*)d_in[6];
    const float* type_emb  = (const float*)d_in[7];
    const float* emb_ln_g  = (const float*)d_in[8];
    const float* emb_ln_b  = (const float*)d_in[9];
    const float* Wq = (const float*)d_in[10];
    const float* bq = (const float*)d_in[11];
    const float* Wk = (const float*)d_in[12];
    const float* bk = (const float*)d_in[13];
    const float* Wv = (const float*)d_in[14];
    const float* bv = (const float*)d_in[15];
    const float* Wo = (const float*)d_in[16];
    const float* bo = (const float*)d_in[17];
    const float* ln1_g = (const float*)d_in[18];
    const float* ln1_b = (const float*)d_in[19];
    const float* W1 = (const float*)d_in[20];
    const float* b1 = (const float*)d_in[21];
    const float* W2 = (const float*)d_in[22];
    const float* b2 = (const float*)d_in[23];
    const float* ln2_g = (const float*)d_in[24];
    const float* ln2_b = (const float*)d_in[25];
    const float* att_Wq = (const float*)d_in[26];
    const float* att_Wk = (const float*)d_in[27];

    float *x, *qkv, *tmp, *sk, *cbias;
    __nv_bfloat16 *wthi, *wtlo, *ahi, *alo, *bhi, *blo;
    cudaGetSymbolAddress((void**)&x,     g_x);
    cudaGetSymbolAddress((void**)&qkv,   g_qkv);
    cudaGetSymbolAddress((void**)&tmp,   g_tmp);
    cudaGetSymbolAddress((void**)&sk,    g_sk);
    cudaGetSymbolAddress((void**)&cbias, g_cbias);
    cudaGetSymbolAddress((void**)&wthi,  g_wthi);
    cudaGetSymbolAddress((void**)&wtlo,  g_wtlo);
    cudaGetSymbolAddress((void**)&ahi,   g_ahi);
    cudaGetSymbolAddress((void**)&alo,   g_alo);
    cudaGetSymbolAddress((void**)&bhi,   g_bhi);
    cudaGetSymbolAddress((void**)&blo,   g_blo);

    cudaFuncSetAttribute(gemm_mma<0>, cudaFuncAttributeMaxDynamicSharedMemorySize, GEMM_SMEM);
    cudaFuncSetAttribute(gemm_mma<1>, cudaFuncAttributeMaxDynamicSharedMemorySize, GEMM_SMEM);
    cudaFuncSetAttribute(gemm_mma<2>, cudaFuncAttributeMaxDynamicSharedMemorySize, GEMM_SMEM);
    cudaFuncSetAttribute(attn_kernel, cudaFuncAttributeMaxDynamicSharedMemorySize, AT_SMEM_BYTES);

    // ---- weight prep ----
    dim3 tb(32, 8);
    for (int l = 0; l < LL; l++) {
        size_t base = (size_t)l * LWSTRIDE;
        const float* srcs[4] = { Wq + (size_t)l*DD*DD, Wk + (size_t)l*DD*DD,
                                 Wv + (size_t)l*DD*DD, Wo + (size_t)l*DD*DD };
        for (int m2 = 0; m2 < 4; m2++) {
            size_t off = base + (size_t)m2 * LW_QKVO;
            transpose_split_kernel<<<dim3(DD/32, DD/32), tb>>>(srcs[m2], wthi + off, wtlo + off, DD, DD);
        }
        transpose_split_kernel<<<dim3(FFD/32, DD/32), tb>>>(W1 + (size_t)l*DD*FFD,
            wthi + base + 4*LW_QKVO, wtlo + base + 4*LW_QKVO, DD, FFD);
        transpose_split_kernel<<<dim3(DD/32, FFD/32), tb>>>(W2 + (size_t)l*FFD*DD,
            wthi + base + 4*LW_QKVO + LW_FF, wtlo + base + 4*LW_QKVO + LW_FF, FFD, DD);
    }
    concat_bias_kernel<<<(LL*QKVN + 255)/256, 256>>>(bq, bk, bv, cbias);

    embed_ln_kernel<<<MM, 256>>>(input_ids, type_ids, word_emb, pos_emb,
                                 type_emb, emb_ln_g, emb_ln_b, x, ahi, alo);

    dim3 gQKV(QKVN/128, MM/128);  // (18, 64)
    dim3 gD(DD/128, MM/128);      // (6, 64)
    dim3 gF(FFD/128, MM/128);     // (24, 64)

    for (int l = 0; l < LL; l++) {
        size_t base = (size_t)l * LWSTRIDE;
        // fused QKV weights: contiguous [2304, 768] at base
        const __nv_bfloat16* wqkv_h = wthi + base;
        const __nv_bfloat16* wqkv_l = wtlo + base;
        const __nv_bfloat16* wo_h = wthi + base + 3*LW_QKVO;  const __nv_bfloat16* wo_l = wtlo + base + 3*LW_QKVO;
        const __nv_bfloat16* w1_h = wthi + base + 4*LW_QKVO;  const __nv_bfloat16* w1_l = wtlo + base + 4*LW_QKVO;
        const __nv_bfloat16* w2_h = wthi + base + 4*LW_QKVO + LW_FF;
        const __nv_bfloat16* w2_l = wtlo + base + 4*LW_QKVO + LW_FF;

        gemm_mma<1><<<gQKV, 256, GEMM_SMEM>>>(ahi, alo, wqkv_h, wqkv_l,
                                              cbias + l*QKVN, qkv, nullptr, nullptr, QKVN, DD);

        attn_kernel<<<dim3(SS/32, HH, BB), 256, AT_SMEM_BYTES>>>(qkv, attn_mask, ahi, alo);

        gemm_mma<0><<<gD, 256, GEMM_SMEM>>>(ahi, alo, wo_h, wo_l, nullptr, tmp,
                                            nullptr, nullptr, DD, DD);
        ln_res_kernel<<<MM, 256>>>(x, tmp, bo + l*DD, ln1_g + l*DD, ln1_b + l*DD, ahi, alo);

        gemm_mma<2><<<gF, 256, GEMM_SMEM>>>(ahi, alo, w1_h, w1_l, b1 + l*FFD,
                                            nullptr, bhi, blo, FFD, DD);
        gemm_mma<0><<<gD, 256, GEMM_SMEM>>>(bhi, blo, w2_h, w2_l, nullptr, tmp,
                                            nullptr, nullptr, DD, FFD);
        ln_res_kernel<<<MM, 256>>>(x, tmp, b2 + l*DD, ln2_g + l*DD, ln2_b + l*DD, ahi, alo);
    }

    sense_k_kernel<<<NSENSE, NATT>>>(sense_emb, att_Wk, sk);
    final_kernel<<<BB, 64>>>(x, location, att_Wq, sk, (float*)d_out);
}